// round 15
// baseline (speedup 1.0000x reference)
#include <cuda_runtime.h>
#include <cuda_bf16.h>
#include <cstdint>

// ---------------------------------------------------------------------------
// Reformer: VSTR_concat + SGTW patch-match style transfer.
//   N=1, C=512, Cs=64, H=W=64, PATCH=3, ALPHA=0.6, SEM_W=0.5, EPS=1e-5
// P = cF_fused^T x sF_fused as 4096x4096x1728 bf16 mma.sync GEMM
// (3-term limb split: hh + hm + mh), fp32 accum.  R = diagonal 3-tap of P
// (the j-taps, same association) precomputed once; argmax sums 3 i-taps of R.
// Coord values bit-identical to the direct 9-tap version.  Near-tie
// locations (gap < 2e-3) re-evaluated EXACTLY in fp32 by refine_kernel.
// ---------------------------------------------------------------------------

typedef unsigned long long u64;

// ---------------- scratch ---------------------------------------------------
__device__ __align__(256) __nv_bfloat16 g_Abf[4096u * 1728u]; // A' [hw_c][K']
__device__ __align__(256) __nv_bfloat16 g_Bbf[4096u * 1728u]; // B' [hw_s][K']
__device__ __align__(256) float g_Af[4096u * 576u];  // exact fused cF [hw][c]
__device__ __align__(256) float g_Bf[4096u * 576u];  // exact fused sF [hw][c]
__device__ __align__(256) float g_P[4096u * 4096u];  // approx correlations 67MB
__device__ __align__(256) float g_R[4096u * 4096u];  // diag 3-tap of P  67MB
__device__ __align__(256) float g_sFt[4096 * 512];
__device__ __align__(256) float g_targT[4096 * 512];
__device__ float g_muC[512], g_scC[512], g_muS[512], g_scS[512];
__device__ float g_E[4096];
__device__ float g_inv[3844];
__device__ int   g_idx[3844];
__device__ int   g_nflag;
__device__ int   g_flags[512];

#define EPS_REF 2e-3f

// ---------------- PTX helpers (sm_80 baseline, compute_103-safe) -----------
__device__ __forceinline__ uint32_t smem_u32(const void* p) {
    uint32_t a;
    asm("{ .reg .u64 t; cvta.to.shared.u64 t, %1; cvt.u32.u64 %0, t; }"
        : "=r"(a) : "l"(p));
    return a;
}
#define CP_ASYNC(dst, src) \
    asm volatile("cp.async.cg.shared.global [%0], [%1], 16;" \
                 :: "r"(dst), "l"(src) : "memory")
#define CP_COMMIT() asm volatile("cp.async.commit_group;" ::: "memory")
#define CP_WAIT1()  asm volatile("cp.async.wait_group 1;" ::: "memory")
#define CP_WAIT0()  asm volatile("cp.async.wait_group 0;" ::: "memory")
#define LDMX4(r, a) \
    asm volatile("ldmatrix.sync.aligned.m8n8.x4.shared.b16 {%0,%1,%2,%3}, [%4];" \
                 : "=r"((r)[0]), "=r"((r)[1]), "=r"((r)[2]), "=r"((r)[3]) : "r"(a))
#define MMA_BF16(d, a, b) \
    asm volatile("mma.sync.aligned.m16n8k16.row.col.f32.bf16.bf16.f32 " \
                 "{%0,%1,%2,%3}, {%4,%5,%6,%7}, {%8,%9}, {%0,%1,%2,%3};" \
                 : "+f"((d)[0]), "+f"((d)[1]), "+f"((d)[2]), "+f"((d)[3]) \
                 : "r"((a)[0]), "r"((a)[1]), "r"((a)[2]), "r"((a)[3]), \
                   "r"((b)[0]), "r"((b)[1]))

// pack (value, index) into a monotonic u64 key: larger value wins, ties -> smaller k
__device__ __forceinline__ u64 pack_key(float v, int k) {
    uint32_t ub = __float_as_uint(v);
    ub = (ub & 0x80000000u) ? ~ub : (ub | 0x80000000u);
    return ((u64)ub << 32) | (uint32_t)(4095 - k);
}
__device__ __forceinline__ float key_val(u64 key) {
    uint32_t u = (uint32_t)(key >> 32);
    u = (u & 0x80000000u) ? (u ^ 0x80000000u) : ~u;
    return __uint_as_float(u);
}
__device__ __forceinline__ int key_idx(u64 key) {
    return 4095 - (int)(key & 0xFFFFFFFFu);
}

// ---------------- per-channel mean / inv-std + init --------------------------
__device__ __forceinline__ float warp_sum(float v) {
    #pragma unroll
    for (int o = 16; o; o >>= 1) v += __shfl_down_sync(0xFFFFFFFFu, v, o);
    return v;
}

__global__ void stats_kernel(const float* __restrict__ cF,
                             const float* __restrict__ sF) {
    int b = blockIdx.x;
    if (b < 16) g_E[b * 256 + threadIdx.x] = 0.f;
    if (b == 16 && threadIdx.x == 0) g_nflag = 0;
    const float* src = (b < 512) ? (cF + (size_t)b * 4096)
                                 : (sF + (size_t)(b - 512) * 4096);
    const float4* src4 = (const float4*)src;
    float s = 0.f, ss = 0.f;
    for (int i = threadIdx.x; i < 1024; i += 256) {
        float4 v = src4[i];
        s  += v.x + v.y + v.z + v.w;
        ss += v.x * v.x + v.y * v.y + v.z * v.z + v.w * v.w;
    }
    __shared__ float shs[8], shss[8];
    s = warp_sum(s); ss = warp_sum(ss);
    int w = threadIdx.x >> 5, l = threadIdx.x & 31;
    if (l == 0) { shs[w] = s; shss[w] = ss; }
    __syncthreads();
    if (threadIdx.x == 0) {
        float S = 0.f, SS = 0.f;
        #pragma unroll
        for (int i = 0; i < 8; i++) { S += shs[i]; SS += shss[i]; }
        float mean = S * (1.0f / 4096.0f);
        float var  = (SS - 4096.0f * mean * mean) * (1.0f / 4095.0f);
        float sc   = rsqrtf(var + 1e-5f);
        if (b < 512) { g_muC[b] = mean; g_scC[b] = sc; }
        else         { g_muS[b - 512] = mean; g_scS[b - 512] = sc; }
    }
}

// ---------------- 2-limb bf16 split -----------------------------------------
__device__ __forceinline__ void split2(float x, __nv_bfloat16& h,
                                       __nv_bfloat16& m) {
    h = __float2bfloat16_rn(x);
    m = __float2bfloat16_rn(x - __bfloat162float(h));
}

// Merged operand builder.  blockIdx.y < 18: A-side (cF); else B-side (sF).
__global__ void build_AB_kernel(const float* __restrict__ cF,
                                const float* __restrict__ cSem,
                                const float* __restrict__ sF,
                                const float* __restrict__ sSem) {
    __shared__ float tile[32][33];
    __shared__ float ep[8][32];
    int hw0 = blockIdx.x * 32;
    int tx = threadIdx.x, ty = threadIdx.y;
    if (blockIdx.y < 18) {
        int c0 = blockIdx.y * 32;
        #pragma unroll
        for (int r = ty; r < 32; r += 8) {
            int c = c0 + r, hw = hw0 + tx;
            float v = (c < 512) ? (cF[c * 4096 + hw] - g_muC[c]) * g_scC[c]
                                : 0.5f * cSem[(c - 512) * 4096 + hw];
            tile[r][tx] = v;
        }
        __syncthreads();
        #pragma unroll
        for (int r = ty; r < 32; r += 8) {
            float v = tile[tx][r];
            __nv_bfloat16 h, m;
            split2(v, h, m);
            __nv_bfloat16* d = g_Abf + (size_t)(hw0 + r) * 1728 + (c0 + tx);
            d[0] = h; d[576] = h; d[1152] = m;
            g_Af[(size_t)(hw0 + r) * 576 + c0 + tx] = v;
        }
    } else {
        int c0 = (blockIdx.y - 18) * 32;
        float e = 0.f;
        #pragma unroll
        for (int r = ty; r < 32; r += 8) {
            int c = c0 + r, hw = hw0 + tx;
            float raw = (c < 512) ? sF[c * 4096 + hw]
                                  : sSem[(c - 512) * 4096 + hw];
            tile[r][tx] = raw;
            float v = (c < 512) ? (raw - g_muS[c]) * g_scS[c] : 0.5f * raw;
            e += v * v;
        }
        ep[ty][tx] = e;
        __syncthreads();
        if (ty == 0) {
            float s = 0.f;
            #pragma unroll
            for (int q = 0; q < 8; q++) s += ep[q][tx];
            atomicAdd(&g_E[hw0 + tx], s);
        }
        int cc = c0 + tx;
        float mu = (cc < 512) ? g_muS[cc] : 0.f;
        float sc = (cc < 512) ? g_scS[cc] : 0.5f;
        #pragma unroll
        for (int r = ty; r < 32; r += 8) {
            float raw = tile[tx][r];
            float v = (raw - mu) * sc;
            __nv_bfloat16 h, m;
            split2(v, h, m);
            __nv_bfloat16* d = g_Bbf + (size_t)(hw0 + r) * 1728 + cc;
            d[0] = h; d[576] = m; d[1152] = h;
            g_Bf[(size_t)(hw0 + r) * 576 + cc] = v;
            if (cc < 512)
                g_sFt[(size_t)(hw0 + r) * 512 + cc] = raw;
        }
    }
}

// ---------------- mma.sync GEMM: P = A' x B'^T, K'=1728 ---------------------
#define GEMM_SMEM (3 * 32768)
#define OFF(r, c) ((uint32_t)(((r) << 7) + (((c) ^ ((r) & 7)) << 4)))
#define ROWB 3456   // bytes per operand row (1728 bf16)

__global__ void __launch_bounds__(256, 2) gemm_mma_kernel() {
    extern __shared__ char sm[];
    uint32_t sbase = smem_u32(sm);
    int tid = threadIdx.x;
    int lane = tid & 31, wid = tid >> 5;
    int wm = wid >> 2, wn = wid & 3;
    int bx = blockIdx.x, by = blockIdx.y;

    if (bx == 0 && by == 0) {       // fold norm computation (once per grid)
        for (int k = tid; k < 3844; k += 256) {
            int ky = k / 62, kx = k - ky * 62;
            float s = 0.f;
            #pragma unroll
            for (int i = 0; i < 3; i++)
                #pragma unroll
                for (int j = 0; j < 3; j++)
                    s += g_E[(ky + i) * 64 + kx + j];
            g_inv[k] = 1.0f / (sqrtf(s) + 1e-7f);
        }
    }

    const char* gA = (const char*)(g_Abf) + (size_t)(by * 128) * ROWB;
    const char* gB = (const char*)(g_Bbf) + (size_t)(bx * 128) * ROWB;

    int cch = tid & 7;
    int rb  = tid >> 3;

    float acc[4][4][4];
    #pragma unroll
    for (int i = 0; i < 4; i++)
        #pragma unroll
        for (int j = 0; j < 4; j++)
            #pragma unroll
            for (int q = 0; q < 4; q++) acc[i][j][q] = 0.f;

#define ISSUE(s, kc) do {                                                    \
    uint32_t sa = sbase + (uint32_t)(s) * 32768u;                            \
    const char* a_ = gA + (size_t)(kc) * 128 + cch * 16;                     \
    const char* b_ = gB + (size_t)(kc) * 128 + cch * 16;                     \
    _Pragma("unroll")                                                        \
    for (int q = 0; q < 4; q++) {                                            \
        int r = rb + q * 32;                                                 \
        CP_ASYNC(sa + OFF(r, cch), a_ + (size_t)r * ROWB);                   \
        CP_ASYNC(sa + 16384u + OFF(r, cch), b_ + (size_t)r * ROWB);          \
    } } while (0)

    ISSUE(0, 0); CP_COMMIT();
    ISSUE(1, 1); CP_COMMIT();

    int ar = wm * 64 + (lane & 15);
    int ac = lane >> 4;
    int br = wn * 32 + (lane & 7) + ((lane >> 4) << 3);
    int bc = (lane >> 3) & 1;

    int scur = 0;
    for (int kc = 0; kc < 27; kc++) {
        CP_WAIT1();
        __syncthreads();
        int snext = scur + 2; if (snext >= 3) snext -= 3;
        if (kc + 2 < 27) ISSUE(snext, kc + 2);
        CP_COMMIT();
        uint32_t stA = sbase + (uint32_t)scur * 32768u;
        uint32_t stB = stA + 16384u;
        #pragma unroll
        for (int kk = 0; kk < 4; kk++) {
            uint32_t af[4][4], bf[4][2];
            #pragma unroll
            for (int mt = 0; mt < 4; mt++) {
                int r = ar + mt * 16, c = 2 * kk + ac;
                LDMX4(af[mt], stA + OFF(r, c));
            }
            #pragma unroll
            for (int nt2 = 0; nt2 < 2; nt2++) {
                uint32_t b4[4];
                int r = br + nt2 * 16, c = 2 * kk + bc;
                LDMX4(b4, stB + OFF(r, c));
                bf[nt2 * 2][0] = b4[0]; bf[nt2 * 2][1] = b4[1];
                bf[nt2 * 2 + 1][0] = b4[2]; bf[nt2 * 2 + 1][1] = b4[3];
            }
            #pragma unroll
            for (int mt = 0; mt < 4; mt++)
                #pragma unroll
                for (int nt = 0; nt < 4; nt++)
                    MMA_BF16(acc[mt][nt], af[mt], bf[nt]);
        }
        if (++scur == 3) scur = 0;
    }
#undef ISSUE

    int mrow = by * 128 + wm * 64 + (lane >> 2);
    int ncol = bx * 128 + wn * 32 + 2 * (lane & 3);
    #pragma unroll
    for (int mt = 0; mt < 4; mt++) {
        #pragma unroll
        for (int nt = 0; nt < 4; nt++) {
            float* p = g_P + (size_t)(mrow + mt * 16) * 4096 + ncol + nt * 8;
            *(float2*)p = make_float2(acc[mt][nt][0], acc[mt][nt][1]);
            *(float2*)(p + 8 * 4096) = make_float2(acc[mt][nt][2], acc[mt][nt][3]);
        }
    }
}

// ---------------- R-pass: diagonal j-tap sums of P ---------------------------
// R[a][b] = (P[a][b] + P[a+1][b+1]) + P[a+2][b+2]  (a = y*64+x, x <= 61;
// b <= 4093; exact association of the former inner j-loop).
// Block = 4 output rows; stages 6 P rows (96KB), 2 blocks/SM.
#define RPASS_SMEM (6 * 4096 * 4)
__global__ void __launch_bounds__(512, 2) rpass_kernel() {
    extern __shared__ char sm[];
    float* rows = (float*)sm;
    uint32_t rows_u32 = smem_u32(rows);
    int a0 = blockIdx.x * 4;
    int tid = threadIdx.x;
    int nrows = min(6, 4096 - a0);
    const char* src = (const char*)(g_P + (size_t)a0 * 4096);
    int nchunk = nrows * 1024;
    for (int t = tid; t < nchunk; t += 512)
        CP_ASYNC(rows_u32 + (uint32_t)t * 16u, src + (size_t)t * 16);
    CP_COMMIT();
    CP_WAIT0();
    __syncthreads();
    #pragma unroll
    for (int r = 0; r < 4; r++) {
        int a = a0 + r;
        int x = a & 63;
        if (x >= 62) continue;                 // never read by argmax
        float* R = g_R + (size_t)a * 4096;
        const float* r0 = rows + r * 4096;
        #pragma unroll
        for (int q = 0; q < 8; q++) {
            int b = tid + q * 512;
            float v = (b <= 4093)
                ? (r0[b] + r0[4096 + b + 1]) + r0[8192 + b + 2] : 0.f;
            R[b] = v;
        }
    }
}

// ---------------- i-tap aggregation on R + top-2 argmax ----------------------
// Per block: 4 locations (y, x0..x0+3).  Stage 4 R rows (64KB) per i;
// accumulate is now ONE LDS + ONE FADD per (location, k, i).
#define ARGMAX_SMEM (4 * 4096 * 4 + 1024)
__global__ void __launch_bounds__(512, 2) argmax_kernel() {
    extern __shared__ char sm[];
    float* rows = (float*)sm;
    uint32_t rows_u32 = smem_u32(rows);
    u64 (*s1)[16] = (u64(*)[16])(sm + 65536);          // [4][16]
    u64 (*s2)[16] = (u64(*)[16])(sm + 65536 + 512);    // [4][16]
    int y = blockIdx.y;
    int x0 = blockIdx.x * 4;
    int na = min(4, 62 - x0);
    int tid = threadIdx.x;
    int lane = tid & 31, wrp = tid >> 5;

    int base[8]; float inv[8];
    #pragma unroll
    for (int m = 0; m < 8; m++) {
        int k = tid + m * 512;
        if (k < 3844) {
            int ky = k / 62, kx = k - ky * 62;
            base[m] = ky * 64 + kx;
            inv[m] = g_inv[k];
        } else { base[m] = 0; inv[m] = 0.f; }
    }

    float acc[4][8];
    #pragma unroll
    for (int aa = 0; aa < 4; aa++)
        #pragma unroll
        for (int m = 0; m < 8; m++) acc[aa][m] = 0.f;

    for (int i = 0; i < 3; i++) {
        __syncthreads();   // previous accumulation done before overwrite
        const char* src = (const char*)(g_R + ((size_t)(y + i) * 64 + x0) * 4096);
        for (int t = tid; t < 4 * 1024; t += 512)
            CP_ASYNC(rows_u32 + (uint32_t)t * 16u, src + (size_t)t * 16);
        CP_COMMIT();
        CP_WAIT0();
        __syncthreads();
        #pragma unroll
        for (int m = 0; m < 8; m++) {
            int b0 = base[m] + i * 64;
            #pragma unroll
            for (int aa = 0; aa < 4; aa++)
                acc[aa][m] += rows[aa * 4096 + b0];
        }
    }

    // phase 1: per-warp top-2 for each location, no block syncs
    #pragma unroll 1
    for (int aa = 0; aa < 4; aa++) {
        u64 k1 = 0, k2 = 0;
        #pragma unroll
        for (int m = 0; m < 8; m++) {
            int k = tid + m * 512;
            if (k < 3844) {
                u64 key = pack_key(acc[aa][m] * inv[m], k);
                if (key > k1) { k2 = k1; k1 = key; }
                else if (key > k2) k2 = key;
            }
        }
        #pragma unroll
        for (int o = 16; o; o >>= 1) {
            u64 o1 = __shfl_down_sync(0xFFFFFFFFu, k1, o);
            u64 o2 = __shfl_down_sync(0xFFFFFFFFu, k2, o);
            if (o1 > k1) { k2 = (k1 > o2) ? k1 : o2; k1 = o1; }
            else if (o1 > k2) k2 = o1;
        }
        if (lane == 0) { s1[aa][wrp] = k1; s2[aa][wrp] = k2; }
    }
    __syncthreads();

    // phase 2: warps 0-3 each merge one location's 16 warp-results
    if (wrp < 4) {
        int aa = wrp;
        u64 k1 = (lane < 16) ? s1[aa][lane] : 0;
        u64 k2 = (lane < 16) ? s2[aa][lane] : 0;
        #pragma unroll
        for (int o = 8; o; o >>= 1) {
            u64 o1 = __shfl_down_sync(0xFFFFFFFFu, k1, o);
            u64 o2 = __shfl_down_sync(0xFFFFFFFFu, k2, o);
            if (o1 > k1) { k2 = (k1 > o2) ? k1 : o2; k1 = o1; }
            else if (o1 > k2) k2 = o1;
        }
        if (lane == 0 && aa < na) {
            int loc = y * 62 + x0 + aa;
            g_idx[loc] = key_idx(k1);
            if (key_val(k1) - key_val(k2) < EPS_REF) {
                int slot = atomicAdd(&g_nflag, 1);
                if (slot < 512) g_flags[slot] = loc;
            }
        }
    }
}

// ---------------- exact fp32 refinement of near-tie locations ---------------
__global__ void refine_kernel() {
    __shared__ float s_v1;
    __shared__ int   s_cnt;
    __shared__ int   s_cand[256];
    __shared__ float s_red[256];
    int bi = blockIdx.x;
    if (bi >= g_nflag || bi >= 512) return;
    int loc = g_flags[bi];
    int y = loc / 62, x = loc - y * 62;
    int tid = threadIdx.x;

    float vloc[16];
    float vmax = -3.4e38f;
    #pragma unroll
    for (int m = 0; m < 16; m++) {
        int k = tid + m * 256;
        float v = -3.4e38f;
        if (k < 3844) {
            int ky = k / 62, kx = k - ky * 62;
            float s = 0.f;
            #pragma unroll
            for (int i = 0; i < 3; i++)
                #pragma unroll
                for (int j = 0; j < 3; j++)
                    s += g_P[(size_t)((y + i) * 64 + x + j) * 4096
                             + (ky + i) * 64 + kx + j];
            v = s * g_inv[k];
        }
        vloc[m] = v;
        vmax = fmaxf(vmax, v);
    }
    s_red[tid] = vmax;
    __syncthreads();
    for (int s = 128; s > 0; s >>= 1) {
        if (tid < s) s_red[tid] = fmaxf(s_red[tid], s_red[tid + s]);
        __syncthreads();
    }
    if (tid == 0) { s_v1 = s_red[0]; s_cnt = 0; }
    __syncthreads();

    float thr = s_v1 - EPS_REF;
    #pragma unroll
    for (int m = 0; m < 16; m++) {
        int k = tid + m * 256;
        if (k < 3844 && vloc[m] >= thr) {
            int slot = atomicAdd(&s_cnt, 1);
            if (slot < 256) s_cand[slot] = k;
        }
    }
    __syncthreads();
    int cnt = min(s_cnt, 256);

    float bestv = -3.4e38f; int bestk = 0x7FFFFFFF;
    for (int c = 0; c < cnt; c++) {
        int k = s_cand[c];
        int ky = k / 62, kx = k - ky * 62;
        float part = 0.f;
        for (int e = tid; e < 5184; e += 256) {
            int tap = e / 576, ch = e - tap * 576;
            int i = tap / 3, j = tap - 3 * i;
            size_t a = (size_t)((y + i) * 64 + x + j) * 576 + ch;
            size_t b = (size_t)((ky + i) * 64 + kx + j) * 576 + ch;
            part += g_Af[a] * g_Bf[b];
        }
        __syncthreads();
        s_red[tid] = part;
        __syncthreads();
        for (int s = 128; s > 0; s >>= 1) {
            if (tid < s) s_red[tid] += s_red[tid + s];
            __syncthreads();
        }
        float ev = s_red[0] * g_inv[k];
        if (ev > bestv || (ev == bestv && k < bestk)) { bestv = ev; bestk = k; }
        __syncthreads();
    }
    if (tid == 0 && cnt > 0) g_idx[loc] = bestk;
}

// ---------------- gather best raw style patches, overlap-add (float4) ------
__global__ void gather_kernel() {
    int hw = blockIdx.x;
    int h = hw >> 6, w = hw & 63;
    int tid = threadIdx.x;           // 128 threads x float4 = 512 channels
    float4 a = make_float4(0.f, 0.f, 0.f, 0.f);
    #pragma unroll
    for (int i = 0; i < 3; i++) {
        int y = h - i;
        if (y < 0 || y >= 62) continue;
        #pragma unroll
        for (int j = 0; j < 3; j++) {
            int x = w - j;
            if (x < 0 || x >= 62) continue;
            int k = g_idx[y * 62 + x];
            int ky = k / 62, kx = k - ky * 62;
            const float4* s = (const float4*)(g_sFt
                + ((size_t)(ky + i) * 64 + kx + j) * 512);
            float4 v = s[tid];
            a.x += v.x; a.y += v.y; a.z += v.z; a.w += v.w;
        }
    }
    ((float4*)(g_targT + (size_t)hw * 512))[tid] = a;
}

// ---------------- transpose back + overlap divide + alpha blend -------------
__global__ void blend_kernel(const float* __restrict__ cF,
                             float* __restrict__ out) {
    __shared__ float tile[32][33];
    int hw0 = blockIdx.x * 32, c0 = blockIdx.y * 32;
    int tx = threadIdx.x, ty = threadIdx.y;
    #pragma unroll
    for (int r = ty; r < 32; r += 8)
        tile[r][tx] = g_targT[(size_t)(hw0 + r) * 512 + c0 + tx];
    __syncthreads();
    #pragma unroll
    for (int r = ty; r < 32; r += 8) {
        int c = c0 + r, hw = hw0 + tx;
        int h = hw >> 6, w = hw & 63;
        int cnth = min(2, h) - max(0, h - 61) + 1;
        int cntw = min(2, w) - max(0, w - 61) + 1;
        float t = tile[tx][r] * (1.0f / (float)(cnth * cntw));
        out[c * 4096 + hw] = 0.6f * t + 0.4f * cF[c * 4096 + hw];
    }
}

// ---------------------------------------------------------------------------
extern "C" void kernel_launch(void* const* d_in, const int* in_sizes, int n_in,
                              void* d_out, int out_size) {
    const float* cF   = (const float*)d_in[0];
    const float* sF   = (const float*)d_in[1];
    const float* cSem = (const float*)d_in[2];
    const float* sSem = (const float*)d_in[3];
    float* out = (float*)d_out;

    cudaFuncSetAttribute(gemm_mma_kernel,
                         cudaFuncAttributeMaxDynamicSharedMemorySize, GEMM_SMEM);
    cudaFuncSetAttribute(rpass_kernel,
                         cudaFuncAttributeMaxDynamicSharedMemorySize, RPASS_SMEM);
    cudaFuncSetAttribute(argmax_kernel,
                         cudaFuncAttributeMaxDynamicSharedMemorySize, ARGMAX_SMEM);

    stats_kernel<<<1024, 256>>>(cF, sF);                              // 1
    build_AB_kernel<<<dim3(128, 36), dim3(32, 8)>>>(cF, cSem, sF, sSem); // 2
    gemm_mma_kernel<<<dim3(32, 32), 256, GEMM_SMEM>>>();              // 3 (+norm)
    rpass_kernel<<<1024, 512, RPASS_SMEM>>>();                        // 4
    argmax_kernel<<<dim3(16, 62), 512, ARGMAX_SMEM>>>();              // 5
    refine_kernel<<<512, 256>>>();                                    // 6
    gather_kernel<<<4096, 128>>>();                                   // 7
    blend_kernel<<<dim3(128, 16), dim3(32, 8)>>>(cF, out);            // 8
}

// round 16
// speedup vs baseline: 1.0380x; 1.0380x over previous
#include <cuda_runtime.h>
#include <cuda_bf16.h>
#include <cstdint>

// ---------------------------------------------------------------------------
// Reformer: VSTR_concat + SGTW patch-match style transfer.
//   N=1, C=512, Cs=64, H=W=64, PATCH=3, ALPHA=0.6, SEM_W=0.5, EPS=1e-5
// P = cF_fused^T x sF_fused as 4096x4096x1728 bf16 mma.sync GEMM
// (3-term limb split: hh + hm + mh), fp32 accum.  Residual worst-case
// < ~1e-3 in coord units; argmax locations with top-2 gap < 2e-3 are
// re-evaluated EXACTLY in fp32 by refine_kernel -> argmax provably exact.
// NOTE: P (67MB) must stay L2-resident through argmax/refine — do NOT add
// any other large intermediate (R15 lesson: 134MB working set -> DRAM).
// ---------------------------------------------------------------------------

typedef unsigned long long u64;

// ---------------- scratch ---------------------------------------------------
__device__ __align__(256) __nv_bfloat16 g_Abf[4096u * 1728u]; // A' [hw_c][K']
__device__ __align__(256) __nv_bfloat16 g_Bbf[4096u * 1728u]; // B' [hw_s][K']
__device__ __align__(256) float g_Af[4096u * 576u];  // exact fused cF [hw][c]
__device__ __align__(256) float g_Bf[4096u * 576u];  // exact fused sF [hw][c]
__device__ __align__(256) float g_P[4096u * 4096u];  // approx correlations 67MB
__device__ __align__(256) float g_sFt[4096 * 512];
__device__ __align__(256) float g_targT[4096 * 512];
__device__ float g_muC[512], g_scC[512], g_muS[512], g_scS[512];
__device__ float g_E[4096];
__device__ float g_inv[3844];
__device__ int   g_idx[3844];
__device__ int   g_nflag;
__device__ int   g_flags[512];

#define EPS_REF 2e-3f

// ---------------- PTX helpers (sm_80 baseline, compute_103-safe) -----------
__device__ __forceinline__ uint32_t smem_u32(const void* p) {
    uint32_t a;
    asm("{ .reg .u64 t; cvta.to.shared.u64 t, %1; cvt.u32.u64 %0, t; }"
        : "=r"(a) : "l"(p));
    return a;
}
#define CP_ASYNC(dst, src) \
    asm volatile("cp.async.cg.shared.global [%0], [%1], 16;" \
                 :: "r"(dst), "l"(src) : "memory")
#define CP_COMMIT() asm volatile("cp.async.commit_group;" ::: "memory")
#define CP_WAIT1()  asm volatile("cp.async.wait_group 1;" ::: "memory")
#define CP_WAIT0()  asm volatile("cp.async.wait_group 0;" ::: "memory")
#define LDMX4(r, a) \
    asm volatile("ldmatrix.sync.aligned.m8n8.x4.shared.b16 {%0,%1,%2,%3}, [%4];" \
                 : "=r"((r)[0]), "=r"((r)[1]), "=r"((r)[2]), "=r"((r)[3]) : "r"(a))
#define MMA_BF16(d, a, b) \
    asm volatile("mma.sync.aligned.m16n8k16.row.col.f32.bf16.bf16.f32 " \
                 "{%0,%1,%2,%3}, {%4,%5,%6,%7}, {%8,%9}, {%0,%1,%2,%3};" \
                 : "+f"((d)[0]), "+f"((d)[1]), "+f"((d)[2]), "+f"((d)[3]) \
                 : "r"((a)[0]), "r"((a)[1]), "r"((a)[2]), "r"((a)[3]), \
                   "r"((b)[0]), "r"((b)[1]))

// pack (value, index) into a monotonic u64 key: larger value wins, ties -> smaller k
__device__ __forceinline__ u64 pack_key(float v, int k) {
    uint32_t ub = __float_as_uint(v);
    ub = (ub & 0x80000000u) ? ~ub : (ub | 0x80000000u);
    return ((u64)ub << 32) | (uint32_t)(4095 - k);
}
__device__ __forceinline__ float key_val(u64 key) {
    uint32_t u = (uint32_t)(key >> 32);
    u = (u & 0x80000000u) ? (u ^ 0x80000000u) : ~u;
    return __uint_as_float(u);
}
__device__ __forceinline__ int key_idx(u64 key) {
    return 4095 - (int)(key & 0xFFFFFFFFu);
}

// ---------------- per-channel mean / inv-std + init --------------------------
__device__ __forceinline__ float warp_sum(float v) {
    #pragma unroll
    for (int o = 16; o; o >>= 1) v += __shfl_down_sync(0xFFFFFFFFu, v, o);
    return v;
}

__global__ void stats_kernel(const float* __restrict__ cF,
                             const float* __restrict__ sF) {
    int b = blockIdx.x;
    if (b < 16) g_E[b * 256 + threadIdx.x] = 0.f;
    if (b == 16 && threadIdx.x == 0) g_nflag = 0;
    const float* src = (b < 512) ? (cF + (size_t)b * 4096)
                                 : (sF + (size_t)(b - 512) * 4096);
    const float4* src4 = (const float4*)src;
    float s = 0.f, ss = 0.f;
    for (int i = threadIdx.x; i < 1024; i += 256) {
        float4 v = src4[i];
        s  += v.x + v.y + v.z + v.w;
        ss += v.x * v.x + v.y * v.y + v.z * v.z + v.w * v.w;
    }
    __shared__ float shs[8], shss[8];
    s = warp_sum(s); ss = warp_sum(ss);
    int w = threadIdx.x >> 5, l = threadIdx.x & 31;
    if (l == 0) { shs[w] = s; shss[w] = ss; }
    __syncthreads();
    if (threadIdx.x == 0) {
        float S = 0.f, SS = 0.f;
        #pragma unroll
        for (int i = 0; i < 8; i++) { S += shs[i]; SS += shss[i]; }
        float mean = S * (1.0f / 4096.0f);
        float var  = (SS - 4096.0f * mean * mean) * (1.0f / 4095.0f);
        float sc   = rsqrtf(var + 1e-5f);
        if (b < 512) { g_muC[b] = mean; g_scC[b] = sc; }
        else         { g_muS[b - 512] = mean; g_scS[b - 512] = sc; }
    }
}

// ---------------- 2-limb bf16 split -----------------------------------------
__device__ __forceinline__ void split2(float x, __nv_bfloat16& h,
                                       __nv_bfloat16& m) {
    h = __float2bfloat16_rn(x);
    m = __float2bfloat16_rn(x - __bfloat162float(h));
}

// Merged operand builder.  blockIdx.y < 18: A-side (cF); else B-side (sF).
__global__ void build_AB_kernel(const float* __restrict__ cF,
                                const float* __restrict__ cSem,
                                const float* __restrict__ sF,
                                const float* __restrict__ sSem) {
    __shared__ float tile[32][33];
    __shared__ float ep[8][32];
    int hw0 = blockIdx.x * 32;
    int tx = threadIdx.x, ty = threadIdx.y;
    if (blockIdx.y < 18) {
        int c0 = blockIdx.y * 32;
        #pragma unroll
        for (int r = ty; r < 32; r += 8) {
            int c = c0 + r, hw = hw0 + tx;
            float v = (c < 512) ? (cF[c * 4096 + hw] - g_muC[c]) * g_scC[c]
                                : 0.5f * cSem[(c - 512) * 4096 + hw];
            tile[r][tx] = v;
        }
        __syncthreads();
        #pragma unroll
        for (int r = ty; r < 32; r += 8) {
            float v = tile[tx][r];
            __nv_bfloat16 h, m;
            split2(v, h, m);
            __nv_bfloat16* d = g_Abf + (size_t)(hw0 + r) * 1728 + (c0 + tx);
            d[0] = h; d[576] = h; d[1152] = m;
            g_Af[(size_t)(hw0 + r) * 576 + c0 + tx] = v;
        }
    } else {
        int c0 = (blockIdx.y - 18) * 32;
        float e = 0.f;
        #pragma unroll
        for (int r = ty; r < 32; r += 8) {
            int c = c0 + r, hw = hw0 + tx;
            float raw = (c < 512) ? sF[c * 4096 + hw]
                                  : sSem[(c - 512) * 4096 + hw];
            tile[r][tx] = raw;
            float v = (c < 512) ? (raw - g_muS[c]) * g_scS[c] : 0.5f * raw;
            e += v * v;
        }
        ep[ty][tx] = e;
        __syncthreads();
        if (ty == 0) {
            float s = 0.f;
            #pragma unroll
            for (int q = 0; q < 8; q++) s += ep[q][tx];
            atomicAdd(&g_E[hw0 + tx], s);
        }
        int cc = c0 + tx;
        float mu = (cc < 512) ? g_muS[cc] : 0.f;
        float sc = (cc < 512) ? g_scS[cc] : 0.5f;
        #pragma unroll
        for (int r = ty; r < 32; r += 8) {
            float raw = tile[tx][r];
            float v = (raw - mu) * sc;
            __nv_bfloat16 h, m;
            split2(v, h, m);
            __nv_bfloat16* d = g_Bbf + (size_t)(hw0 + r) * 1728 + cc;
            d[0] = h; d[576] = m; d[1152] = h;
            g_Bf[(size_t)(hw0 + r) * 576 + cc] = v;
            if (cc < 512)
                g_sFt[(size_t)(hw0 + r) * 512 + cc] = raw;
        }
    }
}

// ---------------- mma.sync GEMM: P = A' x B'^T, K'=1728 ---------------------
#define GEMM_SMEM (3 * 32768)
#define OFF(r, c) ((uint32_t)(((r) << 7) + (((c) ^ ((r) & 7)) << 4)))
#define ROWB 3456   // bytes per operand row (1728 bf16)

__global__ void __launch_bounds__(256, 2) gemm_mma_kernel() {
    extern __shared__ char sm[];
    uint32_t sbase = smem_u32(sm);
    int tid = threadIdx.x;
    int lane = tid & 31, wid = tid >> 5;
    int wm = wid >> 2, wn = wid & 3;
    int bx = blockIdx.x, by = blockIdx.y;

    if (bx == 0 && by == 0) {       // fold norm computation (once per grid)
        for (int k = tid; k < 3844; k += 256) {
            int ky = k / 62, kx = k - ky * 62;
            float s = 0.f;
            #pragma unroll
            for (int i = 0; i < 3; i++)
                #pragma unroll
                for (int j = 0; j < 3; j++)
                    s += g_E[(ky + i) * 64 + kx + j];
            g_inv[k] = 1.0f / (sqrtf(s) + 1e-7f);
        }
    }

    const char* gA = (const char*)(g_Abf) + (size_t)(by * 128) * ROWB;
    const char* gB = (const char*)(g_Bbf) + (size_t)(bx * 128) * ROWB;

    int cch = tid & 7;
    int rb  = tid >> 3;

    float acc[4][4][4];
    #pragma unroll
    for (int i = 0; i < 4; i++)
        #pragma unroll
        for (int j = 0; j < 4; j++)
            #pragma unroll
            for (int q = 0; q < 4; q++) acc[i][j][q] = 0.f;

#define ISSUE(s, kc) do {                                                    \
    uint32_t sa = sbase + (uint32_t)(s) * 32768u;                            \
    const char* a_ = gA + (size_t)(kc) * 128 + cch * 16;                     \
    const char* b_ = gB + (size_t)(kc) * 128 + cch * 16;                     \
    _Pragma("unroll")                                                        \
    for (int q = 0; q < 4; q++) {                                            \
        int r = rb + q * 32;                                                 \
        CP_ASYNC(sa + OFF(r, cch), a_ + (size_t)r * ROWB);                   \
        CP_ASYNC(sa + 16384u + OFF(r, cch), b_ + (size_t)r * ROWB);          \
    } } while (0)

    ISSUE(0, 0); CP_COMMIT();
    ISSUE(1, 1); CP_COMMIT();

    int ar = wm * 64 + (lane & 15);
    int ac = lane >> 4;
    int br = wn * 32 + (lane & 7) + ((lane >> 4) << 3);
    int bc = (lane >> 3) & 1;

    int scur = 0;
    for (int kc = 0; kc < 27; kc++) {
        CP_WAIT1();
        __syncthreads();
        int snext = scur + 2; if (snext >= 3) snext -= 3;
        if (kc + 2 < 27) ISSUE(snext, kc + 2);
        CP_COMMIT();
        uint32_t stA = sbase + (uint32_t)scur * 32768u;
        uint32_t stB = stA + 16384u;
        #pragma unroll
        for (int kk = 0; kk < 4; kk++) {
            uint32_t af[4][4], bf[4][2];
            #pragma unroll
            for (int mt = 0; mt < 4; mt++) {
                int r = ar + mt * 16, c = 2 * kk + ac;
                LDMX4(af[mt], stA + OFF(r, c));
            }
            #pragma unroll
            for (int nt2 = 0; nt2 < 2; nt2++) {
                uint32_t b4[4];
                int r = br + nt2 * 16, c = 2 * kk + bc;
                LDMX4(b4, stB + OFF(r, c));
                bf[nt2 * 2][0] = b4[0]; bf[nt2 * 2][1] = b4[1];
                bf[nt2 * 2 + 1][0] = b4[2]; bf[nt2 * 2 + 1][1] = b4[3];
            }
            #pragma unroll
            for (int mt = 0; mt < 4; mt++)
                #pragma unroll
                for (int nt = 0; nt < 4; nt++)
                    MMA_BF16(acc[mt][nt], af[mt], bf[nt]);
        }
        if (++scur == 3) scur = 0;
    }
#undef ISSUE

    int mrow = by * 128 + wm * 64 + (lane >> 2);
    int ncol = bx * 128 + wn * 32 + 2 * (lane & 3);
    #pragma unroll
    for (int mt = 0; mt < 4; mt++) {
        #pragma unroll
        for (int nt = 0; nt < 4; nt++) {
            float* p = g_P + (size_t)(mrow + mt * 16) * 4096 + ncol + nt * 8;
            *(float2*)p = make_float2(acc[mt][nt][0], acc[mt][nt][1]);
            *(float2*)(p + 8 * 4096) = make_float2(acc[mt][nt][2], acc[mt][nt][3]);
        }
    }
}

// ---------------- 9-tap aggregation + top-2 argmax, 4 locations/block -------
// cp.async staging + SINGLE-sync final reduction (best measured config:
// 512 threads, 2 blocks/SM; implicit cross-block overlap).
#define ARGMAX_SMEM (98304 + 1024)
__global__ void __launch_bounds__(512, 2) argmax_kernel() {
    extern __shared__ char sm[];
    float* rows = (float*)sm;
    uint32_t rows_u32 = smem_u32(rows);
    u64 (*s1)[16] = (u64(*)[16])(sm + 98304);          // [4][16]
    u64 (*s2)[16] = (u64(*)[16])(sm + 98304 + 512);    // [4][16]
    int y = blockIdx.y;
    int x0 = blockIdx.x * 4;
    int na = min(4, 62 - x0);
    int nr = na + 2;
    int tid = threadIdx.x;
    int lane = tid & 31, wrp = tid >> 5;

    int base[8]; float inv[8];
    #pragma unroll
    for (int m = 0; m < 8; m++) {
        int k = tid + m * 512;
        if (k < 3844) {
            int ky = k / 62, kx = k - ky * 62;
            base[m] = ky * 64 + kx;
            inv[m] = g_inv[k];
        } else { base[m] = 0; inv[m] = 0.f; }
    }

    float acc[4][8];
    #pragma unroll
    for (int aa = 0; aa < 4; aa++)
        #pragma unroll
        for (int m = 0; m < 8; m++) acc[aa][m] = 0.f;

    for (int i = 0; i < 3; i++) {
        __syncthreads();   // previous accumulation done before overwrite
        const char* src = (const char*)(g_P + ((size_t)(y + i) * 64 + x0) * 4096);
        int nchunk = nr * 1024;                 // 16B chunks
        for (int t = tid; t < nchunk; t += 512)
            CP_ASYNC(rows_u32 + (uint32_t)t * 16u, src + (size_t)t * 16);
        CP_COMMIT();
        CP_WAIT0();
        __syncthreads();
        #pragma unroll
        for (int m = 0; m < 8; m++) {
            int b0 = base[m] + i * 64;
            #pragma unroll
            for (int aa = 0; aa < 4; aa++) {
                acc[aa][m] += rows[(aa + 0) * 4096 + b0 + 0]
                            + rows[(aa + 1) * 4096 + b0 + 1]
                            + rows[(aa + 2) * 4096 + b0 + 2];
            }
        }
    }

    // phase 1: per-warp top-2 for each location, no block syncs
    #pragma unroll 1
    for (int aa = 0; aa < 4; aa++) {
        u64 k1 = 0, k2 = 0;
        #pragma unroll
        for (int m = 0; m < 8; m++) {
            int k = tid + m * 512;
            if (k < 3844) {
                u64 key = pack_key(acc[aa][m] * inv[m], k);
                if (key > k1) { k2 = k1; k1 = key; }
                else if (key > k2) k2 = key;
            }
        }
        #pragma unroll
        for (int o = 16; o; o >>= 1) {
            u64 o1 = __shfl_down_sync(0xFFFFFFFFu, k1, o);
            u64 o2 = __shfl_down_sync(0xFFFFFFFFu, k2, o);
            if (o1 > k1) { k2 = (k1 > o2) ? k1 : o2; k1 = o1; }
            else if (o1 > k2) k2 = o1;
        }
        if (lane == 0) { s1[aa][wrp] = k1; s2[aa][wrp] = k2; }
    }
    __syncthreads();

    // phase 2: warps 0-3 each merge one location's 16 warp-results
    if (wrp < 4) {
        int aa = wrp;
        u64 k1 = (lane < 16) ? s1[aa][lane] : 0;
        u64 k2 = (lane < 16) ? s2[aa][lane] : 0;
        #pragma unroll
        for (int o = 8; o; o >>= 1) {
            u64 o1 = __shfl_down_sync(0xFFFFFFFFu, k1, o);
            u64 o2 = __shfl_down_sync(0xFFFFFFFFu, k2, o);
            if (o1 > k1) { k2 = (k1 > o2) ? k1 : o2; k1 = o1; }
            else if (o1 > k2) k2 = o1;
        }
        if (lane == 0 && aa < na) {
            int loc = y * 62 + x0 + aa;
            g_idx[loc] = key_idx(k1);
            if (key_val(k1) - key_val(k2) < EPS_REF) {
                int slot = atomicAdd(&g_nflag, 1);
                if (slot < 512) g_flags[slot] = loc;
            }
        }
    }
}

// ---------------- exact fp32 refinement of near-tie locations ---------------
__global__ void refine_kernel() {
    __shared__ float s_v1;
    __shared__ int   s_cnt;
    __shared__ int   s_cand[256];
    __shared__ float s_red[256];
    int bi = blockIdx.x;
    if (bi >= g_nflag || bi >= 512) return;
    int loc = g_flags[bi];
    int y = loc / 62, x = loc - y * 62;
    int tid = threadIdx.x;

    float vloc[16];
    float vmax = -3.4e38f;
    #pragma unroll
    for (int m = 0; m < 16; m++) {
        int k = tid + m * 256;
        float v = -3.4e38f;
        if (k < 3844) {
            int ky = k / 62, kx = k - ky * 62;
            float s = 0.f;
            #pragma unroll
            for (int i = 0; i < 3; i++)
                #pragma unroll
                for (int j = 0; j < 3; j++)
                    s += g_P[(size_t)((y + i) * 64 + x + j) * 4096
                             + (ky + i) * 64 + kx + j];
            v = s * g_inv[k];
        }
        vloc[m] = v;
        vmax = fmaxf(vmax, v);
    }
    s_red[tid] = vmax;
    __syncthreads();
    for (int s = 128; s > 0; s >>= 1) {
        if (tid < s) s_red[tid] = fmaxf(s_red[tid], s_red[tid + s]);
        __syncthreads();
    }
    if (tid == 0) { s_v1 = s_red[0]; s_cnt = 0; }
    __syncthreads();

    float thr = s_v1 - EPS_REF;
    #pragma unroll
    for (int m = 0; m < 16; m++) {
        int k = tid + m * 256;
        if (k < 3844 && vloc[m] >= thr) {
            int slot = atomicAdd(&s_cnt, 1);
            if (slot < 256) s_cand[slot] = k;
        }
    }
    __syncthreads();
    int cnt = min(s_cnt, 256);

    float bestv = -3.4e38f; int bestk = 0x7FFFFFFF;
    for (int c = 0; c < cnt; c++) {
        int k = s_cand[c];
        int ky = k / 62, kx = k - ky * 62;
        float part = 0.f;
        for (int e = tid; e < 5184; e += 256) {
            int tap = e / 576, ch = e - tap * 576;
            int i = tap / 3, j = tap - 3 * i;
            size_t a = (size_t)((y + i) * 64 + x + j) * 576 + ch;
            size_t b = (size_t)((ky + i) * 64 + kx + j) * 576 + ch;
            part += g_Af[a] * g_Bf[b];
        }
        __syncthreads();
        s_red[tid] = part;
        __syncthreads();
        for (int s = 128; s > 0; s >>= 1) {
            if (tid < s) s_red[tid] += s_red[tid + s];
            __syncthreads();
        }
        float ev = s_red[0] * g_inv[k];
        if (ev > bestv || (ev == bestv && k < bestk)) { bestv = ev; bestk = k; }
        __syncthreads();
    }
    if (tid == 0 && cnt > 0) g_idx[loc] = bestk;
}

// ---------------- gather best raw style patches, overlap-add (float4) ------
__global__ void gather_kernel() {
    int hw = blockIdx.x;
    int h = hw >> 6, w = hw & 63;
    int tid = threadIdx.x;           // 128 threads x float4 = 512 channels
    float4 a = make_float4(0.f, 0.f, 0.f, 0.f);
    #pragma unroll
    for (int i = 0; i < 3; i++) {
        int y = h - i;
        if (y < 0 || y >= 62) continue;
        #pragma unroll
        for (int j = 0; j < 3; j++) {
            int x = w - j;
            if (x < 0 || x >= 62) continue;
            int k = g_idx[y * 62 + x];
            int ky = k / 62, kx = k - ky * 62;
            const float4* s = (const float4*)(g_sFt
                + ((size_t)(ky + i) * 64 + kx + j) * 512);
            float4 v = s[tid];
            a.x += v.x; a.y += v.y; a.z += v.z; a.w += v.w;
        }
    }
    ((float4*)(g_targT + (size_t)hw * 512))[tid] = a;
}

// ---------------- transpose back + overlap divide + alpha blend -------------
__global__ void blend_kernel(const float* __restrict__ cF,
                             float* __restrict__ out) {
    __shared__ float tile[32][33];
    int hw0 = blockIdx.x * 32, c0 = blockIdx.y * 32;
    int tx = threadIdx.x, ty = threadIdx.y;
    #pragma unroll
    for (int r = ty; r < 32; r += 8)
        tile[r][tx] = g_targT[(size_t)(hw0 + r) * 512 + c0 + tx];
    __syncthreads();
    #pragma unroll
    for (int r = ty; r < 32; r += 8) {
        int c = c0 + r, hw = hw0 + tx;
        int h = hw >> 6, w = hw & 63;
        int cnth = min(2, h) - max(0, h - 61) + 1;
        int cntw = min(2, w) - max(0, w - 61) + 1;
        float t = tile[tx][r] * (1.0f / (float)(cnth * cntw));
        out[c * 4096 + hw] = 0.6f * t + 0.4f * cF[c * 4096 + hw];
    }
}

// ---------------------------------------------------------------------------
extern "C" void kernel_launch(void* const* d_in, const int* in_sizes, int n_in,
                              void* d_out, int out_size) {
    const float* cF   = (const float*)d_in[0];
    const float* sF   = (const float*)d_in[1];
    const float* cSem = (const float*)d_in[2];
    const float* sSem = (const float*)d_in[3];
    float* out = (float*)d_out;

    cudaFuncSetAttribute(gemm_mma_kernel,
                         cudaFuncAttributeMaxDynamicSharedMemorySize, GEMM_SMEM);
    cudaFuncSetAttribute(argmax_kernel,
                         cudaFuncAttributeMaxDynamicSharedMemorySize, ARGMAX_SMEM);

    stats_kernel<<<1024, 256>>>(cF, sF);                              // 1
    build_AB_kernel<<<dim3(128, 36), dim3(32, 8)>>>(cF, cSem, sF, sSem); // 2
    gemm_mma_kernel<<<dim3(32, 32), 256, GEMM_SMEM>>>();              // 3 (+norm)
    argmax_kernel<<<dim3(16, 62), 512, ARGMAX_SMEM>>>();              // 4
    refine_kernel<<<512, 256>>>();                                    // 5
    gather_kernel<<<4096, 128>>>();                                   // 6
    blend_kernel<<<dim3(128, 16), dim3(32, 8)>>>(cF, out);            // 7
}